// round 16
// baseline (speedup 1.0000x reference)
#include <cuda_runtime.h>
#include <stdint.h>
#include <math_constants.h>

// QueryDepthPoint: depth-constrained radius search.  B=8, N=16384, M=2048,
// NSAMPLE=64, DIS_Z=0.5.  Output: f32 buffer, idx (B,M,64) at [0,1048576),
// pts_cnt (B,M) at [1048576,1064960).
//
// R13-R15: per-chunk efficiency changes all neutral at ~27us; occ ~34% with
// warps to spare => wall time dominated by straggler warps' SERIAL chunk
// chains. R16: split each query across 4 warps (block=query); each warp
// scans one quarter (<=32 chunks) capped at 64 local matches into smem
// staging; merge preserves index order. Straggler serial chain /4.

#define QB 8
#define QN 16384
#define QM 2048
#define QNS 64
#define QDIS_Z 0.5f
#define CHUNK 128
#define NCHUNK (QN / CHUNK)            // 128 chunks per batch row
#define QCHUNK (NCHUNK / 4)            // 32 chunks per quarter

__device__ float2 g_bounds[QB * NCHUNK];   // [b][chunk] = (min, max) of z1

__global__ void __launch_bounds__(256)
bounds_kernel(const float* __restrict__ xyz1)
{
    const int warp = (blockIdx.x * blockDim.x + threadIdx.x) >> 5;  // 0..1023
    const int lane = threadIdx.x & 31;
    if (warp >= QB * NCHUNK) return;
    const int b = warp >> 7;
    const int chunk = warp & (NCHUNK - 1);
    const float* __restrict__ z1 = xyz1 + b * 3 * QN + 2 * QN + chunk * CHUNK;

    float mn =  CUDART_INF_F, mx = -CUDART_INF_F;
    #pragma unroll
    for (int i = 0; i < 4; i++) {
        float v = z1[i * 32 + lane];
        mn = fminf(mn, v);
        mx = fmaxf(mx, v);
    }
    #pragma unroll
    for (int off = 16; off; off >>= 1) {
        mn = fminf(mn, __shfl_xor_sync(0xFFFFFFFFu, mn, off));
        mx = fmaxf(mx, __shfl_xor_sync(0xFFFFFFFFu, mx, off));
    }
    if (lane == 0)
        g_bounds[b * NCHUNK + chunk] = make_float2(mn, mx);
}

__global__ void __launch_bounds__(128)
qdp_kernel(const float* __restrict__ xyz1, int n1,
           const float* __restrict__ xyz2, int n2,
           float* __restrict__ idx_out,
           float* __restrict__ cnt_out)
{
    __shared__ float stage[4 * QNS];   // per-quarter first-64 matches (as f32)
    __shared__ int   scnt[4];          // per-quarter capped counts

    const int q    = threadIdx.x >> 5;        // quarter 0..3
    const int lane = threadIdx.x & 31;
    const int query = blockIdx.x;             // 0..16383
    const int b = query / QM;
    const int m = query - b * QM;

    const int z1_base = b * 3 * QN + 2 * QN;
    const float* __restrict__ z1 =
        (z1_base + QN <= n1) ? (xyz1 + z1_base) : xyz1;
    int z2_i = b * 3 * QM + 2 * QM + m;
    if (z2_i >= n2) z2_i = (n2 > 0) ? (n2 - 1) : 0;
    const float z2v = __ldg(&xyz2[z2_i]);

    const unsigned full = 0xFFFFFFFFu;
    const unsigned lt_mask = (lane == 0) ? 0u : (0xFFFFFFFFu >> (32 - lane));

    // Candidate chunks of this quarter: ONE ballot (32 chunks).
    // Widened by 5e-4: (v - z2) rounding can never cause a false skip.
    const float lo = z2v - (QDIS_Z + 5e-4f);
    const float hi = z2v + (QDIS_Z + 5e-4f);
    const float2 mb = g_bounds[b * NCHUNK + q * QCHUNK + lane];
    unsigned cm = __ballot_sync(full, (mb.x < hi) && (mb.y > lo));

    float* __restrict__ st = stage + q * QNS;
    int lcnt = 0;                              // warp-uniform

    int cur = -1;
    if (cm) { cur = __ffs(cm) - 1; cm &= cm - 1; }
    float4 vcur = make_float4(0.f, 0.f, 0.f, 0.f);
    if (cur >= 0)
        vcur = __ldg((const float4*)(z1 + (q * QCHUNK + cur) * CHUNK) + lane);

    while (cur >= 0) {                         // warp-uniform
        int nxt = -1;
        if (cm) { nxt = __ffs(cm) - 1; cm &= cm - 1; }
        float4 vnxt = vcur;
        if (nxt >= 0)                          // prefetch next candidate
            vnxt = __ldg((const float4*)(z1 + (q * QCHUNK + nxt) * CHUNK) + lane);

        const int j0 = (q * QCHUNK + cur) * CHUNK;
        unsigned m4 = (fabsf(vcur.x - z2v) < QDIS_Z ? 1u : 0u)
                    | (fabsf(vcur.y - z2v) < QDIS_Z ? 2u : 0u)
                    | (fabsf(vcur.z - z2v) < QDIS_Z ? 4u : 0u)
                    | (fabsf(vcur.w - z2v) < QDIS_Z ? 8u : 0u);
        unsigned B0 = __ballot_sync(full, m4 & 1u);
        unsigned B1 = __ballot_sync(full, m4 & 2u);
        unsigned B2 = __ballot_sync(full, m4 & 4u);
        unsigned B3 = __ballot_sync(full, m4 & 8u);

        if (B0 | B1 | B2 | B3) {               // warp-uniform
            int p = lcnt + __popc(B0 & lt_mask) + __popc(B1 & lt_mask)
                         + __popc(B2 & lt_mask) + __popc(B3 & lt_mask);
            const int j = j0 + 4 * lane;
            if (m4 & 1u) { if (p < QNS) st[p] = (float)(j    ); p++; }
            if (m4 & 2u) { if (p < QNS) st[p] = (float)(j + 1); p++; }
            if (m4 & 4u) { if (p < QNS) st[p] = (float)(j + 2); p++; }
            if (m4 & 8u) { if (p < QNS) st[p] = (float)(j + 3); p++; }
            lcnt += __popc(B0) + __popc(B1) + __popc(B2) + __popc(B3);
            if (lcnt >= QNS) break;            // quarter saturated
        }
        cur = nxt;
        vcur = vnxt;
    }
    if (lane == 0)
        scnt[q] = (lcnt > QNS) ? QNS : lcnt;
    __syncthreads();

    // ---- Merge quarters in index order (exact reference semantics) ----
    const int c0 = scnt[0], c1 = scnt[1], c2 = scnt[2], c3 = scnt[3];
    const int tot = c0 + c1 + c2 + c3;
    const int pts = (tot > QNS) ? QNS : tot;   // == min(true_total, 64)

    float fill = 0.0f;                          // first match overall (or 0)
    if      (c0) fill = stage[0];
    else if (c1) fill = stage[QNS];
    else if (c2) fill = stage[2 * QNS];
    else if (c3) fill = stage[3 * QNS];

    if (threadIdx.x < QNS) {
        const int s = threadIdx.x;
        float val = fill;                       // ball-query fill convention
        if (s < pts) {
            if      (s < c0)           val = stage[s];
            else if (s < c0 + c1)      val = stage[QNS     + s - c0];
            else if (s < c0 + c1 + c2) val = stage[2 * QNS + s - c0 - c1];
            else                       val = stage[3 * QNS + s - c0 - c1 - c2];
        }
        idx_out[(size_t)query * QNS + s] = val;
        if (s == 0)
            cnt_out[query] = (float)pts;
    }
}

extern "C" void kernel_launch(void* const* d_in, const int* in_sizes, int n_in,
                              void* d_out, int out_size) {
    const int E1 = QB * 3 * QN;   // 393216 elements (xyz1)
    const int E2 = QB * 3 * QM;   // 49152 elements (xyz2)

    const float* xyz1 = nullptr;
    const float* xyz2 = nullptr;
    for (int i = 0; i < n_in; i++) {
        const int sz = in_sizes[i];
        if ((sz == E1 || sz == E1 * 4) && !xyz1) xyz1 = (const float*)d_in[i];
        else if ((sz == E2 || sz == E2 * 4) && !xyz2) xyz2 = (const float*)d_in[i];
    }
    if ((!xyz1 || !xyz2) && n_in >= 2) {
        if (in_sizes[0] >= in_sizes[1]) {
            if (!xyz1) xyz1 = (const float*)d_in[0];
            if (!xyz2) xyz2 = (const float*)d_in[1];
        } else {
            if (!xyz1) xyz1 = (const float*)d_in[1];
            if (!xyz2) xyz2 = (const float*)d_in[0];
        }
    }
    if (!xyz1 && n_in >= 1) xyz1 = (const float*)d_in[0];
    if (!xyz2) xyz2 = xyz1;

    float* idx_out = (float*)d_out;                  // [0, 1048576)
    float* cnt_out = (float*)d_out + QB * QM * QNS;  // [1048576, 1064960)

    // Kernel 1: per-128-chunk z1 bounds (1024 warps).
    bounds_kernel<<<(QB * NCHUNK * 32 + 255) / 256, 256>>>(xyz1);

    // Kernel 2: one block (4 warps) per query.
    qdp_kernel<<<QB * QM, 128>>>(xyz1, E1, xyz2, E2, idx_out, cnt_out);
}

// round 17
// speedup vs baseline: 1.2880x; 1.2880x over previous
#include <cuda_runtime.h>
#include <stdint.h>
#include <math_constants.h>

// QueryDepthPoint: depth-constrained radius search.  B=8, N=16384, M=2048,
// NSAMPLE=64, DIS_Z=0.5.  Output: f32, idx (B,M,64) at [0,1048576),
// pts_cnt (B,M) at [1048576,1064960).
//
// R13-R16 established: tail stragglers scan ~90 chunks SERIALLY and every
// chunk read is an L2 hit (~234cyc) because B300 flushes L1D per launch.
// R17: block(1024thr)=64 queries of one batch; z1 row (64KB) staged in smem
// once; 32 warps WORK-STEAL queries; scan from LDS (~29cyc) -> straggler
// chain ~8x cheaper; prefilter+compaction unchanged (proven exact).

#define QB 8
#define QN 16384
#define QM 2048
#define QNS 64
#define QDIS_Z 0.5f
#define CHUNK 128
#define NCHUNK (QN / CHUNK)            // 128 chunks per batch row
#define QPB 64                          // queries per block
#define BPB (QM / QPB)                  // 32 blocks per batch

__device__ float2 g_bounds[QB * NCHUNK];   // [b][chunk] = (min, max) of z1

__global__ void __launch_bounds__(256)
bounds_kernel(const float* __restrict__ xyz1)
{
    const int warp = (blockIdx.x * blockDim.x + threadIdx.x) >> 5;  // 0..1023
    const int lane = threadIdx.x & 31;
    if (warp >= QB * NCHUNK) return;
    const int b = warp >> 7;
    const int chunk = warp & (NCHUNK - 1);
    const float* __restrict__ z1 = xyz1 + b * 3 * QN + 2 * QN + chunk * CHUNK;

    float mn =  CUDART_INF_F, mx = -CUDART_INF_F;
    #pragma unroll
    for (int i = 0; i < 4; i++) {
        float v = z1[i * 32 + lane];
        mn = fminf(mn, v);
        mx = fmaxf(mx, v);
    }
    #pragma unroll
    for (int off = 16; off; off >>= 1) {
        mn = fminf(mn, __shfl_xor_sync(0xFFFFFFFFu, mn, off));
        mx = fmaxf(mx, __shfl_xor_sync(0xFFFFFFFFu, mx, off));
    }
    if (lane == 0)
        g_bounds[b * NCHUNK + chunk] = make_float2(mn, mx);
}

// Dynamic smem layout: [0,65536) z1 row; [65536,66560) bounds; [66560] qhead.
#define SMEM_BYTES (65536 + 1024 + 128)

__global__ void __launch_bounds__(1024, 2)
qdp_kernel(const float* __restrict__ xyz1, int n1,
           const float* __restrict__ xyz2, int n2,
           float* __restrict__ idx_out,
           float* __restrict__ cnt_out)
{
    extern __shared__ char sm[];
    float*  sz1  = (float*)sm;                    // 16384 floats
    float2* sbnd = (float2*)(sm + 65536);         // 128 float2
    int*    qhead = (int*)(sm + 65536 + 1024);

    const int b  = blockIdx.x >> 5;               // batch (32 blocks/batch)
    const int q0 = (blockIdx.x & (BPB - 1)) * QPB;
    const int lane = threadIdx.x & 31;
    const unsigned full = 0xFFFFFFFFu;
    const unsigned lt_mask = (lane == 0) ? 0u : (0xFFFFFFFFu >> (32 - lane));

    // ---- Stage z1 row (64KB) into smem, coalesced float4 ----
    {
        const int z1_base = b * 3 * QN + 2 * QN;
        const float4* __restrict__ src = (const float4*)
            (((z1_base + QN) <= n1) ? (xyz1 + z1_base) : xyz1);
        float4* dst = (float4*)sz1;
        #pragma unroll
        for (int k = 0; k < 4; k++)
            dst[threadIdx.x + k * 1024] = __ldg(src + threadIdx.x + k * 1024);
    }
    if (threadIdx.x < NCHUNK)
        sbnd[threadIdx.x] = g_bounds[b * NCHUNK + threadIdx.x];
    if (threadIdx.x == 0)
        *qhead = 0;
    __syncthreads();

    // ---- Work-steal queries ----
    for (;;) {
        int t = 0;
        if (lane == 0) t = atomicAdd(qhead, 1);
        t = __shfl_sync(full, t, 0);
        if (t >= QPB) break;
        const int m = q0 + t;
        const int query = b * QM + m;

        int z2_i = b * 3 * QM + 2 * QM + m;
        if (z2_i >= n2) z2_i = (n2 > 0) ? (n2 - 1) : 0;
        const float z2v = __ldg(&xyz2[z2_i]);

        float* __restrict__ out = idx_out + (size_t)query * QNS;

        // Candidate-chunk mask (4 ballots over 128 chunks); widened 5e-4
        // so (v - z2) rounding can never cause a false skip.
        const float lo = z2v - (QDIS_Z + 5e-4f);
        const float hi = z2v + (QDIS_Z + 5e-4f);
        unsigned long long c01, c23;
        {
            float2 b0 = sbnd[lane];
            float2 b1 = sbnd[32 + lane];
            float2 b2 = sbnd[64 + lane];
            float2 b3 = sbnd[96 + lane];
            unsigned w0 = __ballot_sync(full, (b0.x < hi) && (b0.y > lo));
            unsigned w1 = __ballot_sync(full, (b1.x < hi) && (b1.y > lo));
            unsigned w2 = __ballot_sync(full, (b2.x < hi) && (b2.y > lo));
            unsigned w3 = __ballot_sync(full, (b3.x < hi) && (b3.y > lo));
            c01 = (unsigned long long)w0 | ((unsigned long long)w1 << 32);
            c23 = (unsigned long long)w2 | ((unsigned long long)w3 << 32);
        }

        int cnt = 0;       // warp-uniform
        int firstj = 0;    // warp-uniform

        #define NEXT_CHUNK(dst_)                                            \
            do {                                                            \
                if (c01) { int _k = __ffsll(c01) - 1; c01 &= c01 - 1;       \
                           (dst_) = _k; }                                   \
                else if (c23) { int _k = __ffsll(c23) - 1; c23 &= c23 - 1;  \
                           (dst_) = 64 + _k; }                              \
                else (dst_) = -1;                                           \
            } while (0)

        int cur;
        NEXT_CHUNK(cur);
        while (cur >= 0) {                 // warp-uniform
            const float4 v = ((const float4*)sz1)[cur * 32 + lane];  // LDS.128
            const int j0 = cur * CHUNK;
            unsigned m4 = (fabsf(v.x - z2v) < QDIS_Z ? 1u : 0u)
                        | (fabsf(v.y - z2v) < QDIS_Z ? 2u : 0u)
                        | (fabsf(v.z - z2v) < QDIS_Z ? 4u : 0u)
                        | (fabsf(v.w - z2v) < QDIS_Z ? 8u : 0u);
            unsigned B0 = __ballot_sync(full, m4 & 1u);
            unsigned B1 = __ballot_sync(full, m4 & 2u);
            unsigned B2 = __ballot_sync(full, m4 & 4u);
            unsigned B3 = __ballot_sync(full, m4 & 8u);

            if (B0 | B1 | B2 | B3) {       // warp-uniform
                int p = cnt + __popc(B0 & lt_mask) + __popc(B1 & lt_mask)
                            + __popc(B2 & lt_mask) + __popc(B3 & lt_mask);
                const int j = j0 + 4 * lane;
                if (m4 & 1u) { if (p < QNS) out[p] = (float)(j    ); p++; }
                if (m4 & 2u) { if (p < QNS) out[p] = (float)(j + 1); p++; }
                if (m4 & 4u) { if (p < QNS) out[p] = (float)(j + 2); p++; }
                if (m4 & 8u) { if (p < QNS) out[p] = (float)(j + 3); p++; }

                if (cnt == 0) {            // overall first match in chunk
                    int best = 1 << 30;
                    if (B0) best = min(best, 4 * (__ffs(B0) - 1));
                    if (B1) best = min(best, 4 * (__ffs(B1) - 1) + 1);
                    if (B2) best = min(best, 4 * (__ffs(B2) - 1) + 2);
                    if (B3) best = min(best, 4 * (__ffs(B3) - 1) + 3);
                    firstj = j0 + best;
                }
                cnt += __popc(B0) + __popc(B1) + __popc(B2) + __popc(B3);
                if (cnt >= QNS) break;     // warp-uniform early exit
            }
            NEXT_CHUNK(cur);
        }
        #undef NEXT_CHUNK

        if (cnt > QNS) cnt = QNS;
        const float fillv = (cnt > 0) ? (float)firstj : 0.0f;
        for (int s = cnt + lane; s < QNS; s += 32)
            out[s] = fillv;
        if (lane == 0)
            cnt_out[query] = (float)cnt;
    }
}

extern "C" void kernel_launch(void* const* d_in, const int* in_sizes, int n_in,
                              void* d_out, int out_size) {
    const int E1 = QB * 3 * QN;   // 393216 elements (xyz1)
    const int E2 = QB * 3 * QM;   // 49152 elements (xyz2)

    const float* xyz1 = nullptr;
    const float* xyz2 = nullptr;
    for (int i = 0; i < n_in; i++) {
        const int sz = in_sizes[i];
        if ((sz == E1 || sz == E1 * 4) && !xyz1) xyz1 = (const float*)d_in[i];
        else if ((sz == E2 || sz == E2 * 4) && !xyz2) xyz2 = (const float*)d_in[i];
    }
    if ((!xyz1 || !xyz2) && n_in >= 2) {
        if (in_sizes[0] >= in_sizes[1]) {
            if (!xyz1) xyz1 = (const float*)d_in[0];
            if (!xyz2) xyz2 = (const float*)d_in[1];
        } else {
            if (!xyz1) xyz1 = (const float*)d_in[1];
            if (!xyz2) xyz2 = (const float*)d_in[0];
        }
    }
    if (!xyz1 && n_in >= 1) xyz1 = (const float*)d_in[0];
    if (!xyz2) xyz2 = xyz1;

    float* idx_out = (float*)d_out;                  // [0, 1048576)
    float* cnt_out = (float*)d_out + QB * QM * QNS;  // [1048576, 1064960)

    // Allow 65.7KB dynamic smem (idempotent; immediate host-side call).
    static_assert(SMEM_BYTES <= 100 * 1024, "smem");
    cudaFuncSetAttribute(qdp_kernel,
                         cudaFuncAttributeMaxDynamicSharedMemorySize,
                         SMEM_BYTES);

    // Kernel 1: per-128-chunk z1 bounds.
    bounds_kernel<<<(QB * NCHUNK * 32 + 255) / 256, 256>>>(xyz1);

    // Kernel 2: 256 blocks x 1024 threads; 64 queries/block, work-stealing.
    qdp_kernel<<<QB * BPB, 1024, SMEM_BYTES>>>(xyz1, E1, xyz2, E2,
                                               idx_out, cnt_out);
}